// round 5
// baseline (speedup 1.0000x reference)
#include <cuda_runtime.h>
#include <cuda_bf16.h>
#include <cstdint>

#define NQ 16384
#define DMODEL 256
#define H 8
#define DH 32
#define M 2048
#define TOPN 32
#define QB 16
#define CHUNK 256
#define NCHUNK (M / CHUNK)
#define KBP 72            // K chunk row pitch in bf16 halves (144B rows)
#define LIST_MAX 128
#define LN_EPS 1e-5f
#define NEG_SLOPE 0.01f
#define MAXIT 20

// smem layout (bytes)
#define SM_KS     0
#define SM_LVAL   (2 * CHUNK * KBP * 2)                 // 73728
#define SM_LIDX   (SM_LVAL + QB * LIST_MAX * 4)         // 81920
#define SM_QS     (SM_LIDX + QB * LIST_MAX * 4)         // 90112
#define SM_CNTQW  (SM_QS + QB * 32 * 4)                 // 92160
#define SM_BASEQW (SM_CNTQW + 16 * 16 * 4)              // 93184
#define SM_SSUM   (SM_BASEQW + 16 * 16 * 4)             // 94208
#define SM_SSQ    (SM_SSUM + 16 * 16 * 4)               // 95232
#define SM_SMX    (SM_SSQ + 16 * 16 * 4)                // 96256
#define SM_PIV    (SM_SMX + 16 * 16 * 4)                // 97280
#define SM_BLO    (SM_PIV + 64)
#define SM_BHI    (SM_BLO + 64)
#define SM_CNT    (SM_BHI + 64)
#define SM_CONV   (SM_CNT + 64)
#define SM_FLAG   (SM_CONV + 64)
#define SM_TOTAL  (SM_FLAG + 64)

// ---------------- scratch (no cudaMalloc allowed) ----------------
__device__ float g_Q[NQ * DMODEL];
__device__ float g_K[M * DMODEL];
__device__ float g_V[M * DMODEL];
__device__ float g_CTX[NQ * DMODEL];
__device__ float g_ATT[NQ * DMODEL];
__device__ float g_X1[NQ * DMODEL];
__device__ float g_HB[NQ * DMODEL];
__device__ float g_FF[NQ * DMODEL];
__device__ __nv_bfloat16 g_Kc[H * M * 64];   // per head/key: 32 hi + 32 lo bf16

// ---------------- helpers ----------------
__device__ __forceinline__ float wredsum(float v) {
    #pragma unroll
    for (int o = 16; o; o >>= 1) v += __shfl_xor_sync(0xffffffffu, v, o);
    return v;
}
__device__ __forceinline__ float wredmax(float v) {
    #pragma unroll
    for (int o = 16; o; o >>= 1) v = fmaxf(v, __shfl_xor_sync(0xffffffffu, v, o));
    return v;
}
__device__ __forceinline__ unsigned f2k(float f) {
    unsigned u = __float_as_uint(f);
    return (u & 0x80000000u) ? ~u : (u | 0x80000000u);
}
__device__ __forceinline__ float k2f(unsigned k) {
    return (k & 0x80000000u) ? __uint_as_float(k & 0x7fffffffu)
                             : __uint_as_float(~k);
}
__device__ __forceinline__ void split2(float x, float y, unsigned& hi, unsigned& lo) {
    __nv_bfloat16 xh = __float2bfloat16_rn(x);
    __nv_bfloat16 yh = __float2bfloat16_rn(y);
    __nv_bfloat16 xl = __float2bfloat16_rn(x - __bfloat162float(xh));
    __nv_bfloat16 yl = __float2bfloat16_rn(y - __bfloat162float(yh));
    hi = (unsigned)__bfloat16_as_ushort(xh) | ((unsigned)__bfloat16_as_ushort(yh) << 16);
    lo = (unsigned)__bfloat16_as_ushort(xl) | ((unsigned)__bfloat16_as_ushort(yl) << 16);
}
__device__ __forceinline__ void mma16816(float& d0, float& d1, float& d2, float& d3,
    unsigned a0, unsigned a1, unsigned a2, unsigned a3, unsigned b0, unsigned b1) {
    asm volatile("mma.sync.aligned.m16n8k16.row.col.f32.bf16.bf16.f32 "
        "{%0,%1,%2,%3},{%4,%5,%6,%7},{%8,%9},{%0,%1,%2,%3};"
        : "+f"(d0), "+f"(d1), "+f"(d2), "+f"(d3)
        : "r"(a0), "r"(a1), "r"(a2), "r"(a3), "r"(b0), "r"(b1));
}
__device__ __forceinline__ void cpa16(unsigned dst, const void* src) {
    asm volatile("cp.async.cg.shared.global [%0], [%1], 16;" :: "r"(dst), "l"(src));
}
#define CPA_COMMIT() asm volatile("cp.async.commit_group;")
#define CPA_WAIT(n)  asm volatile("cp.async.wait_group %0;" :: "n"(n))

// one full MMA sweep over K (all chunks), calling body(c0,c1,c2,c3,gk) per n-tile.
// c0,c1 belong to query g (keys gk, gk+1); c2,c3 to query g+8.
template <typename F>
__device__ __forceinline__ void kpass(
    const __nv_bfloat16* __restrict__ Kh, unsigned ks_base,
    const __nv_bfloat16* __restrict__ ks, int tid, int w, int g, int tq,
    const unsigned (&ah)[2][4], const unsigned (&al)[2][4], F&& body)
{
    #pragma unroll
    for (int r = 0; r < 4; ++r) {
        int s = tid + 512 * r, key = s >> 3, part = s & 7;
        cpa16(ks_base + key * 144 + part * 16, Kh + ((size_t)key * 64 + part * 8));
    }
    CPA_COMMIT();
    #pragma unroll 1
    for (int c = 0; c < NCHUNK; ++c) {
        if (c + 1 < NCHUNK) {
            unsigned dbase = ks_base + ((c + 1) & 1) * (CHUNK * KBP * 2);
            const __nv_bfloat16* src = Kh + (size_t)(c + 1) * CHUNK * 64;
            #pragma unroll
            for (int r = 0; r < 4; ++r) {
                int s = tid + 512 * r, key = s >> 3, part = s & 7;
                cpa16(dbase + key * 144 + part * 16, src + ((size_t)key * 64 + part * 8));
            }
            CPA_COMMIT();
            CPA_WAIT(1);
        } else {
            CPA_WAIT(0);
        }
        __syncthreads();
        const __nv_bfloat16* kb = ks + (c & 1) * (CHUNK * KBP);
        #pragma unroll
        for (int nt = 0; nt < 2; ++nt) {
            float c0 = 0.f, c1 = 0.f, c2 = 0.f, c3 = 0.f;
            const __nv_bfloat16* krp = kb + (w * 16 + nt * 8 + g) * KBP;
            #pragma unroll
            for (int s = 0; s < 2; ++s) {
                int ko = s * 16 + tq * 2;
                unsigned b0h = *(const unsigned*)&krp[ko];
                unsigned b1h = *(const unsigned*)&krp[ko + 8];
                unsigned b0l = *(const unsigned*)&krp[32 + ko];
                unsigned b1l = *(const unsigned*)&krp[32 + ko + 8];
                mma16816(c0, c1, c2, c3, ah[s][0], ah[s][1], ah[s][2], ah[s][3], b0h, b1h);
                mma16816(c0, c1, c2, c3, ah[s][0], ah[s][1], ah[s][2], ah[s][3], b0l, b1l);
                mma16816(c0, c1, c2, c3, al[s][0], al[s][1], al[s][2], al[s][3], b0h, b1h);
            }
            int gk = c * CHUNK + w * 16 + nt * 8 + tq * 2;
            body(c0, c1, c2, c3, gk);
        }
        __syncthreads();
    }
}

// ---------------- K pre-conversion: fp32 -> bf16 hi/lo ----------------
__global__ __launch_bounds__(256) void convK(const float* __restrict__ K,
                                             __nv_bfloat16* __restrict__ Kc)
{
    int t = blockIdx.x * 256 + threadIdx.x;   // t < M*H
    int key = t >> 3, h = t & 7;
    const float* src = K + (size_t)key * DMODEL + h * DH;
    __nv_bfloat16* dst = Kc + ((size_t)h * M + key) * 64;
    #pragma unroll
    for (int d = 0; d < 32; d += 2) {
        unsigned hi, lo;
        split2(src[d], src[d + 1], hi, lo);
        *(unsigned*)&dst[d]      = hi;
        *(unsigned*)&dst[32 + d] = lo;
    }
}

// ---------------- SGEMM: C[N,256] = A[N,256] @ W[256,256]^T + bias ----------------
template <int ACT>
__global__ __launch_bounds__(256) void sgemm_nt(
    const float* __restrict__ A, const float* __restrict__ W,
    const float* __restrict__ bias, float* __restrict__ C, int N)
{
    __shared__ __align__(16) float As[8 * 128];
    __shared__ __align__(16) float Bs[8 * 128];
    const int tid = threadIdx.x;
    const int m0 = blockIdx.x * 128;
    const int n0 = blockIdx.y * 128;
    const int tr = tid >> 4;
    const int tc = tid & 15;
    const int lr = tid >> 1;
    const int lc = (tid & 1) * 4;

    float acc[8][8];
    #pragma unroll
    for (int i = 0; i < 8; ++i)
        #pragma unroll
        for (int j = 0; j < 8; ++j) acc[i][j] = 0.f;

    const float* Ag = A + (size_t)(m0 + lr) * 256 + lc;
    const float* Wg = W + (size_t)(n0 + lr) * 256 + lc;

    for (int k0 = 0; k0 < 256; k0 += 8) {
        float4 a4 = *(const float4*)(Ag + k0);
        float4 w4 = *(const float4*)(Wg + k0);
        __syncthreads();
        As[(lc + 0) * 128 + lr] = a4.x; As[(lc + 1) * 128 + lr] = a4.y;
        As[(lc + 2) * 128 + lr] = a4.z; As[(lc + 3) * 128 + lr] = a4.w;
        Bs[(lc + 0) * 128 + lr] = w4.x; Bs[(lc + 1) * 128 + lr] = w4.y;
        Bs[(lc + 2) * 128 + lr] = w4.z; Bs[(lc + 3) * 128 + lr] = w4.w;
        __syncthreads();
        #pragma unroll
        for (int kk = 0; kk < 8; ++kk) {
            float ra[8], rb[8];
            #pragma unroll
            for (int i = 0; i < 8; i += 4) {
                float4 t = *(const float4*)&As[kk * 128 + tr * 8 + i];
                ra[i] = t.x; ra[i + 1] = t.y; ra[i + 2] = t.z; ra[i + 3] = t.w;
            }
            #pragma unroll
            for (int j = 0; j < 8; j += 4) {
                float4 t = *(const float4*)&Bs[kk * 128 + tc * 8 + j];
                rb[j] = t.x; rb[j + 1] = t.y; rb[j + 2] = t.z; rb[j + 3] = t.w;
            }
            #pragma unroll
            for (int i = 0; i < 8; ++i)
                #pragma unroll
                for (int j = 0; j < 8; ++j) acc[i][j] += ra[i] * rb[j];
        }
    }
    #pragma unroll
    for (int i = 0; i < 8; ++i) {
        int m = m0 + tr * 8 + i;
        #pragma unroll
        for (int j = 0; j < 8; j += 4) {
            int n = n0 + tc * 8 + j;
            float4 o;
            o.x = acc[i][j + 0] + bias[n + 0];
            o.y = acc[i][j + 1] + bias[n + 1];
            o.z = acc[i][j + 2] + bias[n + 2];
            o.w = acc[i][j + 3] + bias[n + 3];
            if (ACT == 1) {
                o.x = o.x >= 0.f ? o.x : NEG_SLOPE * o.x;
                o.y = o.y >= 0.f ? o.y : NEG_SLOPE * o.y;
                o.z = o.z >= 0.f ? o.z : NEG_SLOPE * o.z;
                o.w = o.w >= 0.f ? o.w : NEG_SLOPE * o.w;
            }
            *(float4*)&C[(size_t)m * 256 + n] = o;
        }
    }
}

// ---------------- fused residual-add + LayerNorm ----------------
__global__ __launch_bounds__(256) void add_ln(
    const float* __restrict__ a, const float* __restrict__ b,
    const float* __restrict__ g, const float* __restrict__ be,
    float* __restrict__ out)
{
    int row = blockIdx.x * 8 + (threadIdx.x >> 5);
    int lane = threadIdx.x & 31;
    const float* ar = a + (size_t)row * DMODEL;
    const float* br = b + (size_t)row * DMODEL;
    float v[8], s = 0.f, sq = 0.f;
    #pragma unroll
    for (int t = 0; t < 8; ++t) {
        int d = lane + 32 * t;
        v[t] = ar[d] + br[d];
        s += v[t]; sq += v[t] * v[t];
    }
    s = wredsum(s); sq = wredsum(sq);
    float mu = s * (1.f / DMODEL);
    float var = sq * (1.f / DMODEL) - mu * mu;
    float r = rsqrtf(var + LN_EPS);
    float* orow = out + (size_t)row * DMODEL;
    #pragma unroll
    for (int t = 0; t < 8; ++t) {
        int d = lane + 32 * t;
        orow[d] = (v[t] - mu) * r * g[d] + be[d];
    }
}

// ---------------- attention: score-recompute, select, sparse softmax*V ----------------
// grid (NQ/QB, H), 512 threads = 16 warps, 2 CTAs/SM (no score array in smem).
__global__ __launch_bounds__(512, 2) void attn_kernel(
    const float* __restrict__ Q, const __nv_bfloat16* __restrict__ Kc,
    const float* __restrict__ V, float* __restrict__ CTX)
{
    extern __shared__ __align__(16) char smraw[];
    __nv_bfloat16* ks = (__nv_bfloat16*)(smraw + SM_KS);
    float* lval   = (float*)(smraw + SM_LVAL);
    int*   lidx   = (int*)(smraw + SM_LIDX);
    float* qs     = (float*)(smraw + SM_QS);
    int*   cntqw  = (int*)(smraw + SM_CNTQW);
    int*   baseqw = (int*)(smraw + SM_BASEQW);
    float* ssum   = (float*)(smraw + SM_SSUM);
    float* ssq    = (float*)(smraw + SM_SSQ);
    float* smx    = (float*)(smraw + SM_SMX);
    float* piv_sh = (float*)(smraw + SM_PIV);
    float* blo_sh = (float*)(smraw + SM_BLO);
    float* bhi_sh = (float*)(smraw + SM_BHI);
    int*   cnt_sh = (int*)(smraw + SM_CNT);
    int*   conv_sh= (int*)(smraw + SM_CONV);
    int*   flag_sh= (int*)(smraw + SM_FLAG);

    const int tid = threadIdx.x, lane = tid & 31, w = tid >> 5;
    const int h = blockIdx.y;
    const int qblock = blockIdx.x * QB;
    const int g = lane >> 2, tq = lane & 3;
    const unsigned qmask = 0xFu << (g * 4);
    const unsigned below = (1u << lane) - 1u;

    // load Q tile, scaled by 1/sqrt(DH)
    const float scale = 0.17677669529663687f;
    for (int i = tid; i < QB * 32; i += 512) {
        int ql = i >> 5, d = i & 31;
        qs[i] = Q[(size_t)(qblock + ql) * DMODEL + h * DH + d] * scale;
    }
    if (tid == 0) flag_sh[0] = 0;
    if (tid < QB) conv_sh[tid] = 0;
    __syncthreads();

    // A fragments (bf16 hi/lo); rows = queries, k = dims
    unsigned ah[2][4], al[2][4];
    #pragma unroll
    for (int s = 0; s < 2; ++s) {
        int cb = s * 16 + tq * 2;
        split2(qs[g * 32 + cb],           qs[g * 32 + cb + 1],       ah[s][0], al[s][0]);
        split2(qs[(g + 8) * 32 + cb],     qs[(g + 8) * 32 + cb + 1], ah[s][1], al[s][1]);
        split2(qs[g * 32 + cb + 8],       qs[g * 32 + cb + 9],       ah[s][2], al[s][2]);
        split2(qs[(g + 8) * 32 + cb + 8], qs[(g + 8) * 32 + cb + 9], ah[s][3], al[s][3]);
    }

    const __nv_bfloat16* Kh = Kc + (size_t)h * M * 64;
    unsigned ks_base = (unsigned)__cvta_generic_to_shared(ks);

    // ---- pass 1: stats ----
    float sum_a = 0.f, sq_a = 0.f, mx_a = -3.3e38f;
    float sum_b = 0.f, sq_b = 0.f, mx_b = -3.3e38f;
    kpass(Kh, ks_base, ks, tid, w, g, tq, ah, al,
        [&](float c0, float c1, float c2, float c3, int gk) {
            sum_a += c0 + c1; sq_a += c0 * c0 + c1 * c1;
            mx_a = fmaxf(mx_a, fmaxf(c0, c1));
            sum_b += c2 + c3; sq_b += c2 * c2 + c3 * c3;
            mx_b = fmaxf(mx_b, fmaxf(c2, c3));
        });
    #pragma unroll
    for (int o = 1; o < 4; o <<= 1) {
        sum_a += __shfl_xor_sync(0xffffffffu, sum_a, o);
        sq_a  += __shfl_xor_sync(0xffffffffu, sq_a, o);
        mx_a   = fmaxf(mx_a, __shfl_xor_sync(0xffffffffu, mx_a, o));
        sum_b += __shfl_xor_sync(0xffffffffu, sum_b, o);
        sq_b  += __shfl_xor_sync(0xffffffffu, sq_b, o);
        mx_b   = fmaxf(mx_b, __shfl_xor_sync(0xffffffffu, mx_b, o));
    }
    if (tq == 0) {
        ssum[g * 16 + w] = sum_a;        ssq[g * 16 + w] = sq_a;        smx[g * 16 + w] = mx_a;
        ssum[(g + 8) * 16 + w] = sum_b;  ssq[(g + 8) * 16 + w] = sq_b;  smx[(g + 8) * 16 + w] = mx_b;
    }
    __syncthreads();

    // warp w owns query w: final stats + initial pivot/bracket
    float sum = (lane < 16) ? ssum[w * 16 + lane] : 0.f;
    float sq  = (lane < 16) ? ssq[w * 16 + lane]  : 0.f;
    float mxq = (lane < 16) ? smx[w * 16 + lane]  : -3.3e38f;
    sum = wredsum(sum); sq = wredsum(sq); mxq = wredmax(mxq);
    float mu = sum * (1.f / (float)M);
    float sg = sqrtf(fmaxf(sq * (1.f / (float)M) - mu * mu, 0.f));
    if (lane == 0) {
        piv_sh[w] = fminf(mu + 1.863f * sg, mxq);
        blo_sh[w] = mu;     // count(mu) ~ M/2 >= TOPN
        bhi_sh[w] = mxq;
    }

    // ---- pivot loop: count pass + per-query freeze/bisect ----
    int pending = 1;
    #pragma unroll 1
    for (int it = 0; it < MAXIT; ++it) {
        __syncthreads();
        float pa = piv_sh[g], pb = piv_sh[g + 8];
        int ca = 0, cb = 0;
        kpass(Kh, ks_base, ks, tid, w, g, tq, ah, al,
            [&](float c0, float c1, float c2, float c3, int gk) {
                ca += (c0 >= pa) + (c1 >= pa);
                cb += (c2 >= pb) + (c3 >= pb);
            });
        #pragma unroll
        for (int o = 1; o < 4; o <<= 1) {
            ca += __shfl_xor_sync(0xffffffffu, ca, o);
            cb += __shfl_xor_sync(0xffffffffu, cb, o);
        }
        if (tq == 0) {
            cntqw[g * 16 + w] = ca;
            cntqw[(g + 8) * 16 + w] = cb;
        }
        __syncthreads();
        // freeze step (warp w handles query w)
        {
            int conv = conv_sh[w];
            int v = (lane < 16) ? cntqw[w * 16 + lane] : 0;
            int incl = v;
            #pragma unroll
            for (int o = 1; o < 16; o <<= 1) {
                int t = __shfl_up_sync(0xffffffffu, incl, o);
                if (lane >= o) incl += t;
            }
            int total = __shfl_sync(0xffffffffu, incl, 15);
            if (!conv) {
                if (total >= TOPN && total <= LIST_MAX) {
                    if (lane < 16) baseqw[w * 16 + lane] = incl - v;
                    if (lane == 0) { cnt_sh[w] = total; conv_sh[w] = 1; }
                } else if (lane == 0) {
                    if (total < TOPN) bhi_sh[w] = piv_sh[w]; else blo_sh[w] = piv_sh[w];
                    piv_sh[w] = 0.5f * (blo_sh[w] + bhi_sh[w]);
                    flag_sh[0] = 1;
                }
            }
        }
        __syncthreads();
        int fr = flag_sh[0];
        __syncthreads();
        if (!fr) { pending = 0; break; }
        if (tid == 0) flag_sh[0] = 0;
    }

    // ---- rare fallback: force-accept blo for unconverged queries ----
    if (pending) {
        if (lane == 0 && !conv_sh[w]) piv_sh[w] = blo_sh[w];
        __syncthreads();
        float pa = piv_sh[g], pb = piv_sh[g + 8];
        int ca = 0, cb = 0;
        kpass(Kh, ks_base, ks, tid, w, g, tq, ah, al,
            [&](float c0, float c1, float c2, float c3, int gk) {
                ca += (c0 >= pa) + (c1 >= pa);
                cb += (c2 >= pb) + (c3 >= pb);
            });
        #pragma unroll
        for (int o = 1; o < 4; o <<= 1) {
            ca += __shfl_xor_sync(0xffffffffu, ca, o);
            cb += __shfl_xor_sync(0xffffffffu, cb, o);
        }
        if (tq == 0) {
            cntqw[g * 16 + w] = ca;
            cntqw[(g + 8) * 16 + w] = cb;
        }
        __syncthreads();
        {
            int conv = conv_sh[w];
            int v = (lane < 16) ? cntqw[w * 16 + lane] : 0;
            int incl = v;
            #pragma unroll
            for (int o = 1; o < 16; o <<= 1) {
                int t = __shfl_up_sync(0xffffffffu, incl, o);
                if (lane >= o) incl += t;
            }
            int total = __shfl_sync(0xffffffffu, incl, 15);
            if (!conv) {
                if (lane < 16) baseqw[w * 16 + lane] = incl - v;
                if (lane == 0) { cnt_sh[w] = total < LIST_MAX ? total : LIST_MAX; conv_sh[w] = 1; }
            }
        }
    }
    __syncthreads();

    // ---- append pass: deterministic ballot-ordered survivor lists ----
    {
        int ba = baseqw[g * 16 + w];
        int bb = baseqw[(g + 8) * 16 + w];
        float pa = piv_sh[g], pb = piv_sh[g + 8];
        kpass(Kh, ks_base, ks, tid, w, g, tq, ah, al,
            [&](float c0, float c1, float c2, float c3, int gk) {
                unsigned b;
                b = __ballot_sync(0xffffffffu, c0 >= pa);
                if (c0 >= pa) {
                    int p = ba + __popc(b & qmask & below);
                    if (p < LIST_MAX) { lval[g * LIST_MAX + p] = c0; lidx[g * LIST_MAX + p] = gk; }
                }
                ba += __popc(b & qmask);
                b = __ballot_sync(0xffffffffu, c1 >= pa);
                if (c1 >= pa) {
                    int p = ba + __popc(b & qmask & below);
                    if (p < LIST_MAX) { lval[g * LIST_MAX + p] = c1; lidx[g * LIST_MAX + p] = gk + 1; }
                }
                ba += __popc(b & qmask);
                b = __ballot_sync(0xffffffffu, c2 >= pb);
                if (c2 >= pb) {
                    int p = bb + __popc(b & qmask & below);
                    if (p < LIST_MAX) { lval[(g + 8) * LIST_MAX + p] = c2; lidx[(g + 8) * LIST_MAX + p] = gk; }
                }
                bb += __popc(b & qmask);
                b = __ballot_sync(0xffffffffu, c3 >= pb);
                if (c3 >= pb) {
                    int p = bb + __popc(b & qmask & below);
                    if (p < LIST_MAX) { lval[(g + 8) * LIST_MAX + p] = c3; lidx[(g + 8) * LIST_MAX + p] = gk + 1; }
                }
                bb += __popc(b & qmask);
            });
    }
    __syncthreads();

    // ---- selection + sparse softmax*V (warp w = query w) ----
    int cnt = cnt_sh[w];
    const float* lv = lval + w * LIST_MAX;
    const int*   li = lidx + w * LIST_MAX;

    // exact rank-32 value via binary search over monotone keys (tie-exact)
    unsigned kv[LIST_MAX / 32];
    #pragma unroll
    for (int t = 0; t < LIST_MAX / 32; ++t) {
        int e = lane + t * 32;
        kv[t] = (e < cnt) ? f2k(lv[e]) : 0u;
    }
    unsigned lo = 0u, hi = f2k(mxq);
    while (lo < hi) {
        unsigned mid = lo + ((hi - lo + 1u) >> 1);
        int c = 0;
        #pragma unroll
        for (int t = 0; t < LIST_MAX / 32; ++t) c += (kv[t] >= mid) ? 1 : 0;
        c = __reduce_add_sync(0xffffffffu, c);
        if (c >= TOPN) lo = mid; else hi = mid - 1u;
    }
    float thr = k2f(lo);

    // sparse softmax * V: lane owns output dim `lane`
    const float* Vh = V + h * DH + lane;
    float den0 = 0.f, den1 = 0.f, den2 = 0.f, den3 = 0.f;
    float cx0 = 0.f, cx1 = 0.f, cx2 = 0.f, cx3 = 0.f;
    int e = 0;
    for (; e + 4 <= cnt; e += 4) {
        float s0 = lv[e], s1 = lv[e + 1], s2 = lv[e + 2], s3 = lv[e + 3];
        int i0 = li[e], i1 = li[e + 1], i2 = li[e + 2], i3 = li[e + 3];
        if (s0 >= thr) { float wt = __expf(s0 - mxq); den0 += wt; cx0 += wt * Vh[(size_t)i0 * DMODEL]; }
        if (s1 >= thr) { float wt = __expf(s1 - mxq); den1 += wt; cx1 += wt * Vh[(size_t)i1 * DMODEL]; }
        if (s2 >= thr) { float wt = __expf(s2 - mxq); den2 += wt; cx2 += wt * Vh[(size_t)i2 * DMODEL]; }
        if (s3 >= thr) { float wt = __expf(s3 - mxq); den3 += wt; cx3 += wt * Vh[(size_t)i3 * DMODEL]; }
    }
    for (; e < cnt; ++e) {
        float s0 = lv[e];
        if (s0 >= thr) { float wt = __expf(s0 - mxq); den0 += wt; cx0 += wt * Vh[(size_t)li[e] * DMODEL]; }
    }
    float den = (den0 + den1) + (den2 + den3);
    float cx  = (cx0 + cx1) + (cx2 + cx3);
    CTX[(size_t)(qblock + w) * DMODEL + h * DH + lane] = cx / den;
}

// ---------------- launch ----------------
extern "C" void kernel_launch(void* const* d_in, const int* in_sizes, int n_in,
                              void* d_out, int out_size)
{
    const float* x   = (const float*)d_in[0];
    const float* Ep  = (const float*)d_in[1];
    const float* Em  = (const float*)d_in[2];
    const float* Wq  = (const float*)d_in[3];
    const float* bq  = (const float*)d_in[4];
    const float* Wk  = (const float*)d_in[5];
    const float* bk  = (const float*)d_in[6];
    const float* Wv  = (const float*)d_in[7];
    const float* bv  = (const float*)d_in[8];
    const float* Wo  = (const float*)d_in[9];
    const float* bo  = (const float*)d_in[10];
    const float* W1  = (const float*)d_in[11];
    const float* b1  = (const float*)d_in[12];
    const float* W2  = (const float*)d_in[13];
    const float* b2  = (const float*)d_in[14];
    const float* g1  = (const float*)d_in[15];
    const float* be1 = (const float*)d_in[16];
    const float* g2  = (const float*)d_in[17];
    const float* be2 = (const float*)d_in[18];
    float* out = (float*)d_out;

    float *Qp, *Kp, *Vp, *CTXp, *ATTp, *X1p, *Hp, *FFp;
    __nv_bfloat16* Kcp;
    cudaGetSymbolAddress((void**)&Qp,  g_Q);
    cudaGetSymbolAddress((void**)&Kp,  g_K);
    cudaGetSymbolAddress((void**)&Vp,  g_V);
    cudaGetSymbolAddress((void**)&CTXp, g_CTX);
    cudaGetSymbolAddress((void**)&ATTp, g_ATT);
    cudaGetSymbolAddress((void**)&X1p, g_X1);
    cudaGetSymbolAddress((void**)&Hp,  g_HB);
    cudaGetSymbolAddress((void**)&FFp, g_FF);
    cudaGetSymbolAddress((void**)&Kcp, g_Kc);

    dim3 gq(NQ / 128, 2), gkv(M / 128, 2);
    sgemm_nt<0><<<gq, 256>>>(x, Wq, bq, Qp, NQ);
    sgemm_nt<0><<<gkv, 256>>>(Ep, Wk, bk, Kp, M);
    sgemm_nt<0><<<gkv, 256>>>(Em, Wv, bv, Vp, M);
    convK<<<(M * H) / 256, 256>>>(Kp, Kcp);

    cudaFuncSetAttribute(attn_kernel, cudaFuncAttributeMaxDynamicSharedMemorySize, SM_TOTAL);
    attn_kernel<<<dim3(NQ / QB, H), 512, SM_TOTAL>>>(Qp, Kcp, Vp, CTXp);

    sgemm_nt<0><<<gq, 256>>>(CTXp, Wo, bo, ATTp, NQ);
    add_ln<<<NQ / 8, 256>>>(x, ATTp, g1, be1, X1p);
    sgemm_nt<1><<<gq, 256>>>(X1p, W1, b1, Hp, NQ);
    sgemm_nt<0><<<gq, 256>>>(Hp, W2, b2, FFp, NQ);
    add_ln<<<NQ / 8, 256>>>(X1p, FFp, g2, be2, out);
}

// round 7
// speedup vs baseline: 1.0420x; 1.0420x over previous
#include <cuda_runtime.h>
#include <cuda_bf16.h>
#include <cstdint>

#define NQ 16384
#define DMODEL 256
#define H 8
#define HS 2              // heads per stage
#define DH 32
#define M 2048
#define TOPN 32
#define QB 16
#define CHUNK 256
#define NCHUNK (M / CHUNK)
#define KBP 72            // K chunk row pitch in bf16 halves (144B rows)
#define SPITCH 260        // staging row pitch (floats), 1040B (16B aligned)
#define ROWP 2056         // B-kernel smem row pitch (floats)
#define LIST_MAX 128
#define LN_EPS 1e-5f
#define NEG_SLOPE 0.01f

// A-kernel smem offsets (bytes)
#define A_KS     0
#define A_STAGE  (2 * CHUNK * KBP * 2)                  // 73728
#define A_QS     (A_STAGE + 2 * QB * SPITCH * 4)        // 107008
#define A_TOTAL  (A_QS + QB * 32 * 4)                   // 109056

// B-kernel smem offsets (bytes)
#define B_ROW    0
#define B_LVAL   (8 * ROWP * 4)                         // 65792
#define B_LIDX   (B_LVAL + 8 * LIST_MAX * 4)            // 69888
#define B_TOTAL  (B_LIDX + 8 * LIST_MAX * 4)            // 73984

// ---------------- scratch (no cudaMalloc allowed) ----------------
__device__ float g_Q[NQ * DMODEL];
__device__ float g_K[M * DMODEL];
__device__ float g_V[M * DMODEL];
__device__ float g_CTX[NQ * DMODEL];
__device__ float g_ATT[NQ * DMODEL];
__device__ float g_X1[NQ * DMODEL];
__device__ float g_HB[NQ * DMODEL];
__device__ float g_FF[NQ * DMODEL];
__device__ __nv_bfloat16 g_Kc[H * M * 64];     // per head/key: 32 hi + 32 lo bf16
__device__ float g_S[HS * NQ * M];             // staged score buffer (256 MB)

// ---------------- helpers ----------------
__device__ __forceinline__ float wredsum(float v) {
    #pragma unroll
    for (int o = 16; o; o >>= 1) v += __shfl_xor_sync(0xffffffffu, v, o);
    return v;
}
__device__ __forceinline__ float wredmax(float v) {
    #pragma unroll
    for (int o = 16; o; o >>= 1) v = fmaxf(v, __shfl_xor_sync(0xffffffffu, v, o));
    return v;
}
__device__ __forceinline__ unsigned f2k(float f) {
    unsigned u = __float_as_uint(f);
    return (u & 0x80000000u) ? ~u : (u | 0x80000000u);
}
__device__ __forceinline__ float k2f(unsigned k) {
    return (k & 0x80000000u) ? __uint_as_float(k & 0x7fffffffu)
                             : __uint_as_float(~k);
}
__device__ __forceinline__ void split2(float x, float y, unsigned& hi, unsigned& lo) {
    __nv_bfloat16 xh = __float2bfloat16_rn(x);
    __nv_bfloat16 yh = __float2bfloat16_rn(y);
    __nv_bfloat16 xl = __float2bfloat16_rn(x - __bfloat162float(xh));
    __nv_bfloat16 yl = __float2bfloat16_rn(y - __bfloat162float(yh));
    hi = (unsigned)__bfloat16_as_ushort(xh) | ((unsigned)__bfloat16_as_ushort(yh) << 16);
    lo = (unsigned)__bfloat16_as_ushort(xl) | ((unsigned)__bfloat16_as_ushort(yl) << 16);
}
__device__ __forceinline__ void mma16816(float& d0, float& d1, float& d2, float& d3,
    unsigned a0, unsigned a1, unsigned a2, unsigned a3, unsigned b0, unsigned b1) {
    asm volatile("mma.sync.aligned.m16n8k16.row.col.f32.bf16.bf16.f32 "
        "{%0,%1,%2,%3},{%4,%5,%6,%7},{%8,%9},{%0,%1,%2,%3};"
        : "+f"(d0), "+f"(d1), "+f"(d2), "+f"(d3)
        : "r"(a0), "r"(a1), "r"(a2), "r"(a3), "r"(b0), "r"(b1));
}
__device__ __forceinline__ void cpa16(unsigned dst, const void* src) {
    asm volatile("cp.async.cg.shared.global [%0], [%1], 16;" :: "r"(dst), "l"(src));
}
#define CPA_COMMIT() asm volatile("cp.async.commit_group;")
#define CPA_WAIT(n)  asm volatile("cp.async.wait_group %0;" :: "n"(n))

// ---------------- K pre-conversion: fp32 -> bf16 hi/lo ----------------
__global__ __launch_bounds__(256) void convK(const float* __restrict__ K,
                                             __nv_bfloat16* __restrict__ Kc)
{
    int t = blockIdx.x * 256 + threadIdx.x;   // t < M*H*4
    int unit = t & 3, h = (t >> 2) & 7, key = t >> 5;
    const float* src = K + (size_t)key * DMODEL + h * DH + unit * 8;
    __nv_bfloat16* dst = Kc + ((size_t)h * M + key) * 64 + unit * 8;
    #pragma unroll
    for (int d = 0; d < 8; d += 2) {
        unsigned hi, lo;
        split2(src[d], src[d + 1], hi, lo);
        *(unsigned*)&dst[d]      = hi;
        *(unsigned*)&dst[32 + d] = lo;
    }
}

// ---------------- SGEMM: C[N,256] = A[N,256] @ W[256,256]^T + bias ----------------
template <int ACT>
__global__ __launch_bounds__(256) void sgemm_nt(
    const float* __restrict__ A, const float* __restrict__ W,
    const float* __restrict__ bias, float* __restrict__ C, int N)
{
    __shared__ __align__(16) float As[8 * 128];
    __shared__ __align__(16) float Bs[8 * 128];
    const int tid = threadIdx.x;
    const int m0 = blockIdx.x * 128;
    const int n0 = blockIdx.y * 128;
    const int tr = tid >> 4;
    const int tc = tid & 15;
    const int lr = tid >> 1;
    const int lc = (tid & 1) * 4;

    float acc[8][8];
    #pragma unroll
    for (int i = 0; i < 8; ++i)
        #pragma unroll
        for (int j = 0; j < 8; ++j) acc[i][j] = 0.f;

    const float* Ag = A + (size_t)(m0 + lr) * 256 + lc;
    const float* Wg = W + (size_t)(n0 + lr) * 256 + lc;

    for (int k0 = 0; k0 < 256; k0 += 8) {
        float4 a4 = *(const float4*)(Ag + k0);
        float4 w4 = *(const float4*)(Wg + k0);
        __syncthreads();
        As[(lc + 0) * 128 + lr] = a4.x; As[(lc + 1) * 128 + lr] = a4.y;
        As[(lc + 2) * 128 + lr] = a4.z; As[(lc + 3) * 128 + lr] = a4.w;
        Bs[(lc + 0) * 128 + lr] = w4.x; Bs[(lc + 1) * 128 + lr] = w4.y;
        Bs[(lc + 2) * 128 + lr] = w4.z; Bs[(lc + 3) * 128 + lr] = w4.w;
        __syncthreads();
        #pragma unroll
        for (int kk = 0; kk < 8; ++kk) {
            float ra[8], rb[8];
            #pragma unroll
            for (int i = 0; i < 8; i += 4) {
                float4 t = *(const float4*)&As[kk * 128 + tr * 8 + i];
                ra[i] = t.x; ra[i + 1] = t.y; ra[i + 2] = t.z; ra[i + 3] = t.w;
            }
            #pragma unroll
            for (int j = 0; j < 8; j += 4) {
                float4 t = *(const float4*)&Bs[kk * 128 + tc * 8 + j];
                rb[j] = t.x; rb[j + 1] = t.y; rb[j + 2] = t.z; rb[j + 3] = t.w;
            }
            #pragma unroll
            for (int i = 0; i < 8; ++i)
                #pragma unroll
                for (int j = 0; j < 8; ++j) acc[i][j] += ra[i] * rb[j];
        }
    }
    #pragma unroll
    for (int i = 0; i < 8; ++i) {
        int m = m0 + tr * 8 + i;
        #pragma unroll
        for (int j = 0; j < 8; j += 4) {
            int n = n0 + tc * 8 + j;
            float4 o;
            o.x = acc[i][j + 0] + bias[n + 0];
            o.y = acc[i][j + 1] + bias[n + 1];
            o.z = acc[i][j + 2] + bias[n + 2];
            o.w = acc[i][j + 3] + bias[n + 3];
            if (ACT == 1) {
                o.x = o.x >= 0.f ? o.x : NEG_SLOPE * o.x;
                o.y = o.y >= 0.f ? o.y : NEG_SLOPE * o.y;
                o.z = o.z >= 0.f ? o.z : NEG_SLOPE * o.z;
                o.w = o.w >= 0.f ? o.w : NEG_SLOPE * o.w;
            }
            *(float4*)&C[(size_t)m * 256 + n] = o;
        }
    }
}

// ---------------- fused residual-add + LayerNorm ----------------
__global__ __launch_bounds__(256) void add_ln(
    const float* __restrict__ a, const float* __restrict__ b,
    const float* __restrict__ g, const float* __restrict__ be,
    float* __restrict__ out)
{
    int row = blockIdx.x * 8 + (threadIdx.x >> 5);
    int lane = threadIdx.x & 31;
    const float* ar = a + (size_t)row * DMODEL;
    const float* br = b + (size_t)row * DMODEL;
    float v[8], s = 0.f, sq = 0.f;
    #pragma unroll
    for (int t = 0; t < 8; ++t) {
        int d = lane + 32 * t;
        v[t] = ar[d] + br[d];
        s += v[t]; sq += v[t] * v[t];
    }
    s = wredsum(s); sq = wredsum(sq);
    float mu = s * (1.f / DMODEL);
    float var = sq * (1.f / DMODEL) - mu * mu;
    float r = rsqrtf(var + LN_EPS);
    float* orow = out + (size_t)row * DMODEL;
    #pragma unroll
    for (int t = 0; t < 8; ++t) {
        int d = lane + 32 * t;
        orow[d] = (v[t] - mu) * r * g[d] + be[d];
    }
}

// ---------------- Kernel A: score GEMM -> global S ----------------
// grid (NQ/QB, HS), 512 threads = 16 warps, 2 CTAs/SM.
__global__ __launch_bounds__(512, 2) void score_kernel(
    const float* __restrict__ Q, const __nv_bfloat16* __restrict__ Kc,
    float* __restrict__ S, int h0)
{
    extern __shared__ __align__(16) char smraw[];
    __nv_bfloat16* ks = (__nv_bfloat16*)(smraw + A_KS);
    float* stage = (float*)(smraw + A_STAGE);
    float* qs    = (float*)(smraw + A_QS);

    const int tid = threadIdx.x, lane = tid & 31, w = tid >> 5;
    const int hl = blockIdx.y;
    const int h = h0 + hl;
    const int qblock = blockIdx.x * QB;
    const int g = lane >> 2, tq = lane & 3;

    const float scale = 0.17677669529663687f;  // 1/sqrt(32)
    for (int i = tid; i < QB * 32; i += 512) {
        int ql = i >> 5, d = i & 31;
        qs[i] = Q[(size_t)(qblock + ql) * DMODEL + h * DH + d] * scale;
    }
    __syncthreads();

    unsigned ah[2][4], al[2][4];
    #pragma unroll
    for (int s = 0; s < 2; ++s) {
        int cb = s * 16 + tq * 2;
        split2(qs[g * 32 + cb],           qs[g * 32 + cb + 1],       ah[s][0], al[s][0]);
        split2(qs[(g + 8) * 32 + cb],     qs[(g + 8) * 32 + cb + 1], ah[s][1], al[s][1]);
        split2(qs[g * 32 + cb + 8],       qs[g * 32 + cb + 9],       ah[s][2], al[s][2]);
        split2(qs[(g + 8) * 32 + cb + 8], qs[(g + 8) * 32 + cb + 9], ah[s][3], al[s][3]);
    }

    const __nv_bfloat16* Kh = Kc + (size_t)h * M * 64;
    unsigned ks_base = (unsigned)__cvta_generic_to_shared(ks);
    float* drow0 = S + ((size_t)(hl * NQ + qblock + w)) * M;

    // prologue: chunk 0 -> buf 0
    #pragma unroll
    for (int r = 0; r < 4; ++r) {
        int s = tid + 512 * r, key = s >> 3, part = s & 7;
        cpa16(ks_base + key * 144 + part * 16, Kh + ((size_t)key * 64 + part * 8));
    }
    CPA_COMMIT();

    #pragma unroll 1
    for (int c = 0; c < NCHUNK; ++c) {
        if (c + 1 < NCHUNK) {
            unsigned dbase = ks_base + ((c + 1) & 1) * (CHUNK * KBP * 2);
            const __nv_bfloat16* src = Kh + (size_t)(c + 1) * CHUNK * 64;
            #pragma unroll
            for (int r = 0; r < 4; ++r) {
                int s = tid + 512 * r, key = s >> 3, part = s & 7;
                cpa16(dbase + key * 144 + part * 16, src + ((size_t)key * 64 + part * 8));
            }
            CPA_COMMIT();
            CPA_WAIT(1);
        } else {
            CPA_WAIT(0);
        }
        __syncthreads();  // chunk c resident; stage[c&1] free

        const __nv_bfloat16* kb = ks + (c & 1) * (CHUNK * KBP);
        float* sb = stage + (c & 1) * QB * SPITCH;
        #pragma unroll
        for (int nt = 0; nt < 2; ++nt) {
            float c0 = 0.f, c1 = 0.f, c2 = 0.f, c3 = 0.f;
            const __nv_bfloat16* krp = kb + (w * 16 + nt * 8 + g) * KBP;
            #pragma unroll
            for (int s = 0; s < 2; ++s) {
                int ko = s * 16 + tq * 2;
                unsigned b0h = *(const unsigned*)&krp[ko];
                unsigned b1h = *(const unsigned*)&krp[ko + 8];
                unsigned b0l = *(const unsigned*)&krp[32 + ko];
                unsigned b1l = *(const unsigned*)&krp[32 + ko + 8];
                mma16816(c0, c1, c2, c3, ah[s][0], ah[s][1], ah[s][2], ah[s][3], b0h, b1h);
                mma16816(c0, c1, c2, c3, ah[s][0], ah[s][1], ah[s][2], ah[s][3], b0l, b1l);
                mma16816(c0, c1, c2, c3, al[s][0], al[s][1], al[s][2], al[s][3], b0h, b1h);
            }
            int col = w * 16 + nt * 8 + tq * 2;
            sb[g * SPITCH + col]           = c0;
            sb[g * SPITCH + col + 1]       = c1;
            sb[(g + 8) * SPITCH + col]     = c2;
            sb[(g + 8) * SPITCH + col + 1] = c3;
        }
        __syncthreads();  // stage[c&1] complete

        // copy: warp w owns query row w (coalesced 128b stores)
        {
            const float* srcrow = sb + w * SPITCH;
            float* drow = drow0 + c * CHUNK;
            #pragma unroll
            for (int j = 0; j < 2; ++j) {
                float4 v = *(const float4*)&srcrow[lane * 4 + 128 * j];
                *(float4*)&drow[lane * 4 + 128 * j] = v;
            }
        }
    }
}

// ---------------- Kernel B: per-(q,h) top-32 select + sparse softmax*V ----------------
// grid (HS*NQ/8), 256 threads = 8 warps, 3 CTAs/SM. Warp-independent (no block syncs).
__global__ __launch_bounds__(256, 3) void select_kernel(
    const float* __restrict__ S, const float* __restrict__ V,
    float* __restrict__ CTX, int h0)
{
    extern __shared__ __align__(16) char smraw[];
    float* rows = (float*)(smraw + B_ROW);
    float* lvs  = (float*)(smraw + B_LVAL);
    int*   lis  = (int*)(smraw + B_LIDX);

    const int lane = threadIdx.x & 31, w = threadIdx.x >> 5;
    const int r = blockIdx.x * 8 + w;
    const int q = r & (NQ - 1);
    const int hl = r >> 14;
    const int h = h0 + hl;

    float* row = rows + w * ROWP;
    float* lval = lvs + w * LIST_MAX;
    int*   lidx = lis + w * LIST_MAX;

    // load row (coalesced LDG.128 -> STS.128), stats fused
    const float* Srow = S + (size_t)r * M;
    float sum = 0.f, sq = 0.f, mx = -3.3e38f;
    #pragma unroll
    for (int j = 0; j < 16; ++j) {
        int idx = j * 128 + lane * 4;
        float4 v = *(const float4*)&Srow[idx];
        *(float4*)&row[idx] = v;
        sum += (v.x + v.y) + (v.z + v.w);
        sq  += v.x * v.x + v.y * v.y + v.z * v.z + v.w * v.w;
        mx = fmaxf(mx, fmaxf(fmaxf(v.x, v.y), fmaxf(v.z, v.w)));
    }
    sum = wredsum(sum); sq = wredsum(sq); mx = wredmax(mx);
    float mu = sum * (1.f / (float)M);
    float sg = sqrtf(fmaxf(sq * (1.f / (float)M) - mu * mu, 0.f));
    __syncwarp();

    // pivot bisection: TOPN <= count(>=piv) <= LIST_MAX
    float blo = -3.3e38f, bhi = mx;
    float piv = fminf(mu + 1.9f * sg, mx);
    int myc = 0;
    bool ok = false;
    for (int it = 0; it < 48; ++it) {
        myc = 0;
        #pragma unroll 4
        for (int i = lane; i < M; i += 32) myc += (row[i] >= piv) ? 1 : 0;
        int c = __reduce_add_sync(0xffffffffu, myc);
        if (c >= TOPN && c <= LIST_MAX) { ok = true; break; }
        if (c < TOPN) bhi = piv; else blo = piv;
        piv = 0.5f * (blo + bhi);
    }
    if (!ok) {
        piv = blo;  // bracket invariant: count(blo) >= TOPN
        myc = 0;
        #pragma unroll 4
        for (int i = lane; i < M; i += 32) myc += (row[i] >= piv) ? 1 : 0;
    }
    int total = __reduce_add_sync(0xffffffffu, myc);

    // de-chained compaction
    int off = myc;
    #pragma unroll
    for (int o = 1; o < 32; o <<= 1) {
        int t = __shfl_up_sync(0xffffffffu, off, o);
        if (lane >= o) off += t;
    }
    off -= myc;
    int p = off;
    #pragma unroll 4
    for (int i = lane; i < M; i += 32) {
        float sv = row[i];
        if (sv >= piv) {
            if (p < LIST_MAX) { lval[p] = sv; lidx[p] = i; }
            ++p;
        }
    }
    int cnt = total < LIST_MAX ? total : LIST_MAX;
    __syncwarp();

    // exact rank-32 threshold (tie-exact) via binary search on monotone keys
    unsigned kv[LIST_MAX / 32];
    #pragma unroll
    for (int t = 0; t < LIST_MAX / 32; ++t) {
        int e = lane + t * 32;
        kv[t] = (e < cnt) ? f2k(lval[e]) : 0u;
    }
    unsigned lo = 0u, hi = f2k(mx);
    while (lo < hi) {
        unsigned mid = lo + ((hi - lo + 1u) >> 1);
        int c = 0;
        #pragma unroll
        for (int t = 0; t < LIST_MAX / 32; ++t) c += (kv[t] >= mid) ? 1 : 0;
        c = __reduce_add_sync(0xffffffffu, c);
        if (c >= TOPN) lo = mid; else hi = mid - 1u;
    }
    float thr = k2f(lo);

    // sparse softmax * V: lane owns output dim `lane`
    const float* Vh = V + h * DH + lane;
    float den0 = 0.f, den1 = 0.f, den2 = 0.f, den3 = 0.f;
    float cx0 = 0.f, cx1 = 0.f, cx2 = 0.f, cx3 = 0.f;
    int e = 0;
    for (; e + 4 <= cnt; e += 4) {
        float s0 = lval[e], s1 = lval[e + 1], s2 = lval[e + 2], s3 = lval[e + 3];
        int i0 = lidx[e], i1 = lidx[e + 1], i2 = lidx[e + 2], i3 = lidx[e + 3];
        if (s0 >= thr) { float wt = __expf(s0 - mx); den0 += wt; cx0 += wt * Vh[(size_t)i0 * DMODEL]; }
        if (s1 >= thr) { float wt = __expf(s1 - mx); den1 += wt; cx1 += wt * Vh[(size_t)i1 * DMODEL]; }
        if (s2 >= thr) { float wt = __expf(s2 - mx); den2 += wt; cx2 += wt * Vh[(size_t)i2 * DMODEL]; }
        if (s3 >= thr) { float wt = __expf(s3 - mx); den3 += wt; cx3 += wt * Vh[(size_t)i3 * DMODEL]; }
    }
    for (; e < cnt; ++e) {
        float s0 = lval[e];
        if (s0 >= thr) { float wt = __expf(s0 - mx); den0 += wt; cx0 += wt * Vh[(size_t)lidx[e] * DMODEL]; }
    }
    float den = (den0 + den1) + (den2 + den3);
    float cx  = (cx0 + cx1) + (cx2 + cx3);
    CTX[(size_t)q * DMODEL + h * DH + lane] = cx / den;
}

// ---------------- launch ----------------
extern "C" void kernel_launch(void* const* d_in, const int* in_sizes, int n_in,
                              void* d_out, int out_size)
{
    const float* x   = (const float*)d_in[0];
    const float* Ep  = (const float*)d_in[1];
    const float* Em  = (const float*)d_in[2];
    const float* Wq  = (const float*)d_in[3];
    const float* bq  = (const float*)d_in[4];
    const float* Wk  = (const float*)d_in[5];
    const float* bk  = (const float*)d_in[6];
    const float* Wv  = (const float*)d_in[7];
    const float* bv  = (const float*)d_in[8];
    const float* Wo  = (const float*)d_in[9];
    const float* bo  = (const float*)d_in[10];
    const float* W1  = (const float*)d_in[11];
    const float* b1  = (const float*)d_in[12];
    const float* W2  = (const float*)d_in[13];
    const float* b2  = (const float*)d_in[14];
    const float* g1  = (const float*)d_in[15];
    const float* be1 = (const float*)d_in[16];
    const float* g2  = (const float*)d_in[17];
    const float* be2 = (const float*)d_in[18];
    float* out = (float*)d_out;

    float *Qp, *Kp, *Vp, *CTXp, *ATTp, *X1p, *Hp, *FFp, *Sp;
    __nv_bfloat16* Kcp;
    cudaGetSymbolAddress((void**)&Qp,  g_Q);
    cudaGetSymbolAddress((void**)&Kp,  g_K);
    cudaGetSymbolAddress((void**)&Vp,  g_V);
    cudaGetSymbolAddress((void**)&CTXp, g_CTX);
    cudaGetSymbolAddress((void**)&ATTp, g_ATT);
    cudaGetSymbolAddress((void**)&X1p, g_X1);
    cudaGetSymbolAddress((void**)&Hp,  g_HB);
    cudaGetSymbolAddress((void**)&FFp, g_FF);
    cudaGetSymbolAddress((void**)&Kcp, g_Kc);
    cudaGetSymbolAddress((void**)&Sp,  g_S);

    dim3 gq(NQ / 128, 2), gkv(M / 128, 2);
    sgemm_nt<0><<<gq, 256>>>(x, Wq, bq, Qp, NQ);
    sgemm_nt<0><<<gkv, 256>>>(Ep, Wk, bk, Kp, M);
    sgemm_nt<0><<<gkv, 256>>>(Em, Wv, bv, Vp, M);
    convK<<<(M * H * 4) / 256, 256>>>(Kp, Kcp);

    cudaFuncSetAttribute(score_kernel, cudaFuncAttributeMaxDynamicSharedMemorySize, A_TOTAL);
    cudaFuncSetAttribute(select_kernel, cudaFuncAttributeMaxDynamicSharedMemorySize, B_TOTAL);
    for (int h0 = 0; h0 < H; h0 += HS) {
        score_kernel<<<dim3(NQ / QB, HS), 512, A_TOTAL>>>(Qp, Kcp, Sp, h0);
        select_kernel<<<(HS * NQ) / 8, 256, B_TOTAL>>>(Sp, Vp, CTXp, h0);
    }

    sgemm_nt<0><<<gq, 256>>>(CTXp, Wo, bo, ATTp, NQ);
    add_ln<<<NQ / 8, 256>>>(x, ATTp, g1, be1, X1p);
    sgemm_nt<1><<<gq, 256>>>(X1p, W1, b1, Hp, NQ);
    sgemm_nt<0><<<gq, 256>>>(Hp, W2, b2, FFp, NQ);
    add_ln<<<NQ / 8, 256>>>(X1p, FFp, g2, be2, out);
}

// round 8
// speedup vs baseline: 1.1537x; 1.1072x over previous
#include <cuda_runtime.h>
#include <cuda_bf16.h>
#include <cstdint>

#define NQ 16384
#define DMODEL 256
#define H 8
#define HS 2              // heads per stage
#define DH 32
#define M 2048
#define TOPN 32
#define QB 16
#define CHUNK 256
#define NCHUNK (M / CHUNK)
#define KBP 72            // K chunk row pitch in bf16 halves (144B rows)
#define SPITCH 260        // staging row pitch (floats)
#define LIST_MAX 128
#define LN_EPS 1e-5f
#define NEG_SLOPE 0.01f

// A-kernel smem offsets (bytes)
#define A_KS     0
#define A_STAGE  (2 * CHUNK * KBP * 2)                  // 73728
#define A_QS     (A_STAGE + 2 * QB * SPITCH * 4)        // 107008
#define A_SSUM   (A_QS + QB * 32 * 4)                   // 109056
#define A_SSQ    (A_SSUM + 16 * 16 * 4)                 // 110080
#define A_SMX    (A_SSQ + 16 * 16 * 4)                  // 111104
#define A_TOTAL  (A_SMX + 16 * 16 * 4)                  // 112128 (2 CTAs/SM)

// ---------------- scratch (no cudaMalloc allowed) ----------------
__device__ float g_Q[NQ * DMODEL];
__device__ float g_K[M * DMODEL];
__device__ float g_V[M * DMODEL];
__device__ float g_CTX[NQ * DMODEL];
__device__ float g_ATT[NQ * DMODEL];
__device__ float g_X1[NQ * DMODEL];
__device__ float g_HB[NQ * DMODEL];
__device__ float g_FF[NQ * DMODEL];
__device__ __nv_bfloat16 g_Kc[H * M * 64];     // per head/key: 32 hi + 32 lo bf16
__device__ float g_S[HS * NQ * M];             // staged score buffer (256 MB)
__device__ float4 g_stat[HS * NQ];             // per-row {sum, sq, max, -}

// ---------------- helpers ----------------
__device__ __forceinline__ float wredsum(float v) {
    #pragma unroll
    for (int o = 16; o; o >>= 1) v += __shfl_xor_sync(0xffffffffu, v, o);
    return v;
}
__device__ __forceinline__ float wredmax(float v) {
    #pragma unroll
    for (int o = 16; o; o >>= 1) v = fmaxf(v, __shfl_xor_sync(0xffffffffu, v, o));
    return v;
}
__device__ __forceinline__ unsigned f2k(float f) {
    unsigned u = __float_as_uint(f);
    return (u & 0x80000000u) ? ~u : (u | 0x80000000u);
}
__device__ __forceinline__ float k2f(unsigned k) {
    return (k & 0x80000000u) ? __uint_as_float(k & 0x7fffffffu)
                             : __uint_as_float(~k);
}
__device__ __forceinline__ void split2(float x, float y, unsigned& hi, unsigned& lo) {
    __nv_bfloat16 xh = __float2bfloat16_rn(x);
    __nv_bfloat16 yh = __float2bfloat16_rn(y);
    __nv_bfloat16 xl = __float2bfloat16_rn(x - __bfloat162float(xh));
    __nv_bfloat16 yl = __float2bfloat16_rn(y - __bfloat162float(yh));
    hi = (unsigned)__bfloat16_as_ushort(xh) | ((unsigned)__bfloat16_as_ushort(yh) << 16);
    lo = (unsigned)__bfloat16_as_ushort(xl) | ((unsigned)__bfloat16_as_ushort(yl) << 16);
}
__device__ __forceinline__ void mma16816(float& d0, float& d1, float& d2, float& d3,
    unsigned a0, unsigned a1, unsigned a2, unsigned a3, unsigned b0, unsigned b1) {
    asm volatile("mma.sync.aligned.m16n8k16.row.col.f32.bf16.bf16.f32 "
        "{%0,%1,%2,%3},{%4,%5,%6,%7},{%8,%9},{%0,%1,%2,%3};"
        : "+f"(d0), "+f"(d1), "+f"(d2), "+f"(d3)
        : "r"(a0), "r"(a1), "r"(a2), "r"(a3), "r"(b0), "r"(b1));
}
__device__ __forceinline__ void cpa16(unsigned dst, const void* src) {
    asm volatile("cp.async.cg.shared.global [%0], [%1], 16;" :: "r"(dst), "l"(src));
}
#define CPA_COMMIT() asm volatile("cp.async.commit_group;")
#define CPA_WAIT(n)  asm volatile("cp.async.wait_group %0;" :: "n"(n))

// ---------------- K pre-conversion: fp32 -> bf16 hi/lo ----------------
__global__ __launch_bounds__(256) void convK(const float* __restrict__ K,
                                             __nv_bfloat16* __restrict__ Kc)
{
    int t = blockIdx.x * 256 + threadIdx.x;   // t < M*H*4
    int unit = t & 3, h = (t >> 2) & 7, key = t >> 5;
    const float* src = K + (size_t)key * DMODEL + h * DH + unit * 8;
    __nv_bfloat16* dst = Kc + ((size_t)h * M + key) * 64 + unit * 8;
    #pragma unroll
    for (int d = 0; d < 8; d += 2) {
        unsigned hi, lo;
        split2(src[d], src[d + 1], hi, lo);
        *(unsigned*)&dst[d]      = hi;
        *(unsigned*)&dst[32 + d] = lo;
    }
}

// ---------------- SGEMM: C[N,256] = A[N,256] @ W[256,256]^T + bias ----------------
template <int ACT>
__global__ __launch_bounds__(256) void sgemm_nt(
    const float* __restrict__ A, const float* __restrict__ W,
    const float* __restrict__ bias, float* __restrict__ C, int N)
{
    __shared__ __align__(16) float As[8 * 128];
    __shared__ __align__(16) float Bs[8 * 128];
    const int tid = threadIdx.x;
    const int m0 = blockIdx.x * 128;
    const int n0 = blockIdx.y * 128;
    const int tr = tid >> 4;
    const int tc = tid & 15;
    const int lr = tid >> 1;
    const int lc = (tid & 1) * 4;

    float acc[8][8];
    #pragma unroll
    for (int i = 0; i < 8; ++i)
        #pragma unroll
        for (int j = 0; j < 8; ++j) acc[i][j] = 0.f;

    const float* Ag = A + (size_t)(m0 + lr) * 256 + lc;
    const float* Wg = W + (size_t)(n0 + lr) * 256 + lc;

    for (int k0 = 0; k0 < 256; k0 += 8) {
        float4 a4 = *(const float4*)(Ag + k0);
        float4 w4 = *(const float4*)(Wg + k0);
        __syncthreads();
        As[(lc + 0) * 128 + lr] = a4.x; As[(lc + 1) * 128 + lr] = a4.y;
        As[(lc + 2) * 128 + lr] = a4.z; As[(lc + 3) * 128 + lr] = a4.w;
        Bs[(lc + 0) * 128 + lr] = w4.x; Bs[(lc + 1) * 128 + lr] = w4.y;
        Bs[(lc + 2) * 128 + lr] = w4.z; Bs[(lc + 3) * 128 + lr] = w4.w;
        __syncthreads();
        #pragma unroll
        for (int kk = 0; kk < 8; ++kk) {
            float ra[8], rb[8];
            #pragma unroll
            for (int i = 0; i < 8; i += 4) {
                float4 t = *(const float4*)&As[kk * 128 + tr * 8 + i];
                ra[i] = t.x; ra[i + 1] = t.y; ra[i + 2] = t.z; ra[i + 3] = t.w;
            }
            #pragma unroll
            for (int j = 0; j < 8; j += 4) {
                float4 t = *(const float4*)&Bs[kk * 128 + tc * 8 + j];
                rb[j] = t.x; rb[j + 1] = t.y; rb[j + 2] = t.z; rb[j + 3] = t.w;
            }
            #pragma unroll
            for (int i = 0; i < 8; ++i)
                #pragma unroll
                for (int j = 0; j < 8; ++j) acc[i][j] += ra[i] * rb[j];
        }
    }
    #pragma unroll
    for (int i = 0; i < 8; ++i) {
        int m = m0 + tr * 8 + i;
        #pragma unroll
        for (int j = 0; j < 8; j += 4) {
            int n = n0 + tc * 8 + j;
            float4 o;
            o.x = acc[i][j + 0] + bias[n + 0];
            o.y = acc[i][j + 1] + bias[n + 1];
            o.z = acc[i][j + 2] + bias[n + 2];
            o.w = acc[i][j + 3] + bias[n + 3];
            if (ACT == 1) {
                o.x = o.x >= 0.f ? o.x : NEG_SLOPE * o.x;
                o.y = o.y >= 0.f ? o.y : NEG_SLOPE * o.y;
                o.z = o.z >= 0.f ? o.z : NEG_SLOPE * o.z;
                o.w = o.w >= 0.f ? o.w : NEG_SLOPE * o.w;
            }
            *(float4*)&C[(size_t)m * 256 + n] = o;
        }
    }
}

// ---------------- fused residual-add + LayerNorm ----------------
__global__ __launch_bounds__(256) void add_ln(
    const float* __restrict__ a, const float* __restrict__ b,
    const float* __restrict__ g, const float* __restrict__ be,
    float* __restrict__ out)
{
    int row = blockIdx.x * 8 + (threadIdx.x >> 5);
    int lane = threadIdx.x & 31;
    const float* ar = a + (size_t)row * DMODEL;
    const float* br = b + (size_t)row * DMODEL;
    float v[8], s = 0.f, sq = 0.f;
    #pragma unroll
    for (int t = 0; t < 8; ++t) {
        int d = lane + 32 * t;
        v[t] = ar[d] + br[d];
        s += v[t]; sq += v[t] * v[t];
    }
    s = wredsum(s); sq = wredsum(sq);
    float mu = s * (1.f / DMODEL);
    float var = sq * (1.f / DMODEL) - mu * mu;
    float r = rsqrtf(var + LN_EPS);
    float* orow = out + (size_t)row * DMODEL;
    #pragma unroll
    for (int t = 0; t < 8; ++t) {
        int d = lane + 32 * t;
        orow[d] = (v[t] - mu) * r * g[d] + be[d];
    }
}

// ---------------- Kernel A: score GEMM -> global S (+ per-row stats) ----------------
// grid (NQ/QB, HS), 512 threads = 16 warps, 2 CTAs/SM.
__global__ __launch_bounds__(512, 2) void score_kernel(
    const float* __restrict__ Q, const __nv_bfloat16* __restrict__ Kc,
    float* __restrict__ S, float4* __restrict__ ST, int h0)
{
    extern __shared__ __align__(16) char smraw[];
    __nv_bfloat16* ks = (__nv_bfloat16*)(smraw + A_KS);
    float* stage = (float*)(smraw + A_STAGE);
    float* qs    = (float*)(smraw + A_QS);
    float* ssum  = (float*)(smraw + A_SSUM);
    float* ssq   = (float*)(smraw + A_SSQ);
    float* smx   = (float*)(smraw + A_SMX);

    const int tid = threadIdx.x, lane = tid & 31, w = tid >> 5;
    const int hl = blockIdx.y;
    const int h = h0 + hl;
    const int qblock = blockIdx.x * QB;
    const int g = lane >> 2, tq = lane & 3;

    const float scale = 0.17677669529663687f;  // 1/sqrt(32)
    for (int i = tid; i < QB * 32; i += 512) {
        int ql = i >> 5, d = i & 31;
        qs[i] = Q[(size_t)(qblock + ql) * DMODEL + h * DH + d] * scale;
    }
    __syncthreads();

    unsigned ah[2][4], al[2][4];
    #pragma unroll
    for (int s = 0; s < 2; ++s) {
        int cb = s * 16 + tq * 2;
        split2(qs[g * 32 + cb],           qs[g * 32 + cb + 1],       ah[s][0], al[s][0]);
        split2(qs[(g + 8) * 32 + cb],     qs[(g + 8) * 32 + cb + 1], ah[s][1], al[s][1]);
        split2(qs[g * 32 + cb + 8],       qs[g * 32 + cb + 9],       ah[s][2], al[s][2]);
        split2(qs[(g + 8) * 32 + cb + 8], qs[(g + 8) * 32 + cb + 9], ah[s][3], al[s][3]);
    }

    const __nv_bfloat16* Kh = Kc + (size_t)h * M * 64;
    unsigned ks_base = (unsigned)__cvta_generic_to_shared(ks);
    float* drow0 = S + ((size_t)(hl * NQ + qblock + w)) * M;

    // prologue: chunk 0 -> buf 0
    #pragma unroll
    for (int r = 0; r < 4; ++r) {
        int s = tid + 512 * r, key = s >> 3, part = s & 7;
        cpa16(ks_base + key * 144 + part * 16, Kh + ((size_t)key * 64 + part * 8));
    }
    CPA_COMMIT();

    float sum_a = 0.f, sq_a = 0.f, mx_a = -3.3e38f;
    float sum_b = 0.f, sq_b = 0.f, mx_b = -3.3e38f;

    #pragma unroll 1
    for (int c = 0; c < NCHUNK; ++c) {
        if (c + 1 < NCHUNK) {
            unsigned dbase = ks_base + ((c + 1) & 1) * (CHUNK * KBP * 2);
            const __nv_bfloat16* src = Kh + (size_t)(c + 1) * CHUNK * 64;
            #pragma unroll
            for (int r = 0; r < 4; ++r) {
                int s = tid + 512 * r, key = s >> 3, part = s & 7;
                cpa16(dbase + key * 144 + part * 16, src + ((size_t)key * 64 + part * 8));
            }
            CPA_COMMIT();
            CPA_WAIT(1);
        } else {
            CPA_WAIT(0);
        }
        __syncthreads();  // chunk c resident; stage[c&1] free

        const __nv_bfloat16* kb = ks + (c & 1) * (CHUNK * KBP);
        float* sb = stage + (c & 1) * QB * SPITCH;
        #pragma unroll
        for (int nt = 0; nt < 2; ++nt) {
            float c0 = 0.f, c1 = 0.f, c2 = 0.f, c3 = 0.f;
            const __nv_bfloat16* krp = kb + (w * 16 + nt * 8 + g) * KBP;
            #pragma unroll
            for (int s = 0; s < 2; ++s) {
                int ko = s * 16 + tq * 2;
                unsigned b0h = *(const unsigned*)&krp[ko];
                unsigned b1h = *(const unsigned*)&krp[ko + 8];
                unsigned b0l = *(const unsigned*)&krp[32 + ko];
                unsigned b1l = *(const unsigned*)&krp[32 + ko + 8];
                mma16816(c0, c1, c2, c3, ah[s][0], ah[s][1], ah[s][2], ah[s][3], b0h, b1h);
                mma16816(c0, c1, c2, c3, ah[s][0], ah[s][1], ah[s][2], ah[s][3], b0l, b1l);
                mma16816(c0, c1, c2, c3, al[s][0], al[s][1], al[s][2], al[s][3], b0h, b1h);
            }
            int col = w * 16 + nt * 8 + tq * 2;
            sb[g * SPITCH + col]           = c0;
            sb[g * SPITCH + col + 1]       = c1;
            sb[(g + 8) * SPITCH + col]     = c2;
            sb[(g + 8) * SPITCH + col + 1] = c3;
            // fused stats: c0,c1 -> query g ; c2,c3 -> query g+8
            sum_a += c0 + c1; sq_a += c0 * c0 + c1 * c1;
            mx_a = fmaxf(mx_a, fmaxf(c0, c1));
            sum_b += c2 + c3; sq_b += c2 * c2 + c3 * c3;
            mx_b = fmaxf(mx_b, fmaxf(c2, c3));
        }
        __syncthreads();  // stage[c&1] complete

        // copy: warp w owns query row w (coalesced 128b stores)
        {
            const float* srcrow = sb + w * SPITCH;
            float* drow = drow0 + c * CHUNK;
            #pragma unroll
            for (int j = 0; j < 2; ++j) {
                float4 v = *(const float4*)&srcrow[lane * 4 + 128 * j];
                *(float4*)&drow[lane * 4 + 128 * j] = v;
            }
        }
    }

    // per-query stats: quad reduce then [query][warp] table
    #pragma unroll
    for (int o = 1; o < 4; o <<= 1) {
        sum_a += __shfl_xor_sync(0xffffffffu, sum_a, o);
        sq_a  += __shfl_xor_sync(0xffffffffu, sq_a, o);
        mx_a   = fmaxf(mx_a, __shfl_xor_sync(0xffffffffu, mx_a, o));
        sum_b += __shfl_xor_sync(0xffffffffu, sum_b, o);
        sq_b  += __shfl_xor_sync(0xffffffffu, sq_b, o);
        mx_b   = fmaxf(mx_b, __shfl_xor_sync(0xffffffffu, mx_b, o));
    }
    if (tq == 0) {
        ssum[g * 16 + w] = sum_a;        ssq[g * 16 + w] = sq_a;        smx[g * 16 + w] = mx_a;
        ssum[(g + 8) * 16 + w] = sum_b;  ssq[(g + 8) * 16 + w] = sq_b;  smx[(g + 8) * 16 + w] = mx_b;
    }
    __syncthreads();

    // warp w finalizes query w and writes stat row
    float s1 = (lane < 16) ? ssum[w * 16 + lane] : 0.f;
    float s2 = (lane < 16) ? ssq[w * 16 + lane]  : 0.f;
    float m  = (lane < 16) ? smx[w * 16 + lane]  : -3.3e38f;
    s1 = wredsum(s1); s2 = wredsum(s2); m = wredmax(m);
    if (lane == 0) ST[hl * NQ + qblock + w] = make_float4(s1, s2, m, 0.f);
}

// ---------------- Kernel B: per-(q,h) top-32 select + sparse softmax*V ----------------
// grid (HS*NQ/8), 256 threads = 8 warps, 4 CTAs/SM. Warp-independent; S rows
// scanned straight from L2 (no smem row), survivors compacted into per-lane
// deterministic segments (order-free set semantics).
__global__ __launch_bounds__(256, 4) void select_kernel(
    const float* __restrict__ S, const float4* __restrict__ ST,
    const float* __restrict__ V, float* __restrict__ CTX, int h0)
{
    __shared__ float lvs[8 * LIST_MAX];
    __shared__ int   lis[8 * LIST_MAX];

    const int lane = threadIdx.x & 31, w = threadIdx.x >> 5;
    const int r = blockIdx.x * 8 + w;
    const int q = r & (NQ - 1);
    const int hl = r >> 14;
    const int h = h0 + hl;

    float* lval = lvs + w * LIST_MAX;
    int*   lidx = lis + w * LIST_MAX;

    const float4* Srow = (const float4*)(S + (size_t)r * M);  // 512 float4s
    float4 st = __ldg(&ST[r]);
    float mx = st.z;
    float mu = st.x * (1.f / (float)M);
    float sg = sqrtf(fmaxf(st.y * (1.f / (float)M) - mu * mu, 0.f));

    // pivot bisection on global row (L2-hot): TOPN <= count <= LIST_MAX
    float blo = -3.3e38f, bhi = mx;
    float piv = fminf(mu + 1.9f * sg, mx);
    int myc = 0;
    bool ok = false;
    for (int it = 0; it < 48; ++it) {
        myc = 0;
        #pragma unroll 4
        for (int j = 0; j < 16; ++j) {
            float4 v = __ldg(&Srow[j * 32 + lane]);
            myc += (v.x >= piv) + (v.y >= piv) + (v.z >= piv) + (v.w >= piv);
        }
        int c = __reduce_add_sync(0xffffffffu, myc);
        if (c >= TOPN && c <= LIST_MAX) { ok = true; break; }
        if (c < TOPN) bhi = piv; else blo = piv;
        piv = 0.5f * (blo + bhi);
    }
    if (!ok) {
        piv = blo;  // bracket invariant: count(blo) >= TOPN
        myc = 0;
        #pragma unroll 4
        for (int j = 0; j < 16; ++j) {
            float4 v = __ldg(&Srow[j * 32 + lane]);
            myc += (v.x >= piv) + (v.y >= piv) + (v.z >= piv) + (v.w >= piv);
        }
    }
    int total = __reduce_add_sync(0xffffffffu, myc);

    // per-lane exclusive prefix -> per-lane survivor segments
    int off = myc;
    #pragma unroll
    for (int o = 1; o < 32; o <<= 1) {
        int t = __shfl_up_sync(0xffffffffu, off, o);
        if (lane >= o) off += t;
    }
    off -= myc;

    // compact pass: re-read row, write survivors deterministically
    int p = off;
    #pragma unroll 4
    for (int j = 0; j < 16; ++j) {
        float4 v = __ldg(&Srow[j * 32 + lane]);
        int base = j * 128 + lane * 4;
        if (v.x >= piv && p < LIST_MAX) { lval[p] = v.x; lidx[p] = base;     ++p; }
        else p += (v.x >= piv);
        if (v.y >= piv && p < LIST_MAX) { lval[p] = v.y; lidx[p] = base + 1; ++p; }
        else p += (v.y >= piv);
        if (v.z >= piv && p < LIST_MAX) { lval[p] = v.z; lidx[p] = base + 2; ++p; }
        else p += (v.z >= piv);
        if (v.w >= piv && p < LIST_MAX) { lval[p] = v.w; lidx[p] = base + 3; ++p; }
        else p += (v.w >= piv);
    }
    int cnt = total < LIST_MAX ? total : LIST_MAX;
    __syncwarp();

    // exact rank-32 threshold (tie-exact), search range [piv, mx]
    unsigned kv[LIST_MAX / 32];
    #pragma unroll
    for (int t = 0; t < LIST_MAX / 32; ++t) {
        int e = lane + t * 32;
        kv[t] = (e < cnt) ? f2k(lval[e]) : 0u;
    }
    unsigned lo = f2k(piv), hi = f2k(mx);
    while (lo < hi) {
        unsigned mid = lo + ((hi - lo + 1u) >> 1);
        int c = 0;
        #pragma unroll
        for (int t = 0; t < LIST_MAX / 32; ++t) c += (kv[t] >= mid) ? 1 : 0;
        c = __reduce_add_sync(0xffffffffu, c);
        if (c >= TOPN) lo = mid; else hi = mid - 1u;
    }
    float thr = k2f(lo);

    // sparse softmax * V: lane owns output dim `lane`
    const float* Vh = V + h * DH + lane;
    float den0 = 0.f, den1 = 0.f, den2 = 0.f, den3 = 0.f;
    float cx0 = 0.f, cx1 = 0.f, cx2 = 0.f, cx3 = 0.f;
    int e = 0;
    for (; e + 4 <= cnt; e += 4) {
        float s0 = lval[e], s1 = lval[e + 1], s2 = lval[e + 2], s3 = lval[e + 3];
        int i0 = lidx[e], i1 = lidx[e + 1], i2 = lidx[e + 2], i3 = lidx[e + 3];
        if (s0 >= thr) { float wt = __expf(s0 - mx); den0 += wt; cx0 += wt * Vh[(size_t)i0 * DMODEL]; }
        if (s1 >= thr) { float wt = __expf(s1 - mx); den1 += wt; cx1 += wt * Vh[(size_t)i1 * DMODEL]; }
        if (s2 >= thr) { float wt = __expf(s2 - mx); den2 += wt; cx2 += wt * Vh[(size_t)i2 * DMODEL]; }
        if (s3 >= thr) { float wt = __expf(s3 - mx); den3 += wt; cx3 += wt * Vh[(size_t)i3 * DMODEL]; }
    }
    for (; e < cnt; ++e) {
        float s0 = lval[e];
        if (s0 >= thr) { float wt = __expf(s0 - mx); den0 += wt; cx0 += wt * Vh[(size_t)lidx[e] * DMODEL]; }
    }
    float den = (den0 + den1) + (den2 + den3);
    float cx  = (cx0 + cx1) + (cx2 + cx3);
    CTX[(size_t)q * DMODEL + h * DH + lane] = cx / den;
}

// ---------------- launch ----------------
extern "C" void kernel_launch(void* const* d_in, const int* in_sizes, int n_in,
                              void* d_out, int out_size)
{
    const float* x   = (const float*)d_in[0];
    const float* Ep  = (const float*)d_in[1];
    const float* Em  = (const float*)d_in[2];
    const float* Wq  = (const float*)d_in[3];
    const float* bq  = (const float*)d_in[4];
    const float* Wk  = (const float*)d_in[5];
    const float* bk  = (const float*)d_in[6];
    const float* Wv  = (const float*)d_in[7];
    const float* bv  = (const float*)d_in[8];
    const float* Wo  = (const float*)d_in[9];
    const float* bo  = (const float*)d_in[10];
    const float* W1  = (const float*)d_in[11];
    const float* b1  = (const float*)d_in[12];
    const float* W2  = (const float*)d_in[13];
    const float* b2  = (const float*)d_in[14];
    const float* g1  = (const float*)d_in[15];
    const float* be1 = (const float*)d_in[16];
    const float* g2  = (const float*)d_in[17];
    const float* be2 = (const float*)d_in[18];
    float* out = (float*)d_out;

    float *Qp, *Kp, *Vp, *CTXp, *ATTp, *X1p, *Hp, *FFp, *Sp;
    float4* STp;
    __nv_bfloat16* Kcp;
    cudaGetSymbolAddress((void**)&Qp,  g_Q);
    cudaGetSymbolAddress((void**)&Kp,  g_K);
    cudaGetSymbolAddress((void**)&Vp,  g_V);
    cudaGetSymbolAddress((void**)&CTXp, g_CTX);
    cudaGetSymbolAddress((void**)&ATTp, g_ATT);
    cudaGetSymbolAddress((void**)&X1p, g_X1);
    cudaGetSymbolAddress((void**)&Hp,  g_HB);
    cudaGetSymbolAddress((void**)&FFp, g_FF);
    cudaGetSymbolAddress((void**)&Kcp, g_Kc);
    cudaGetSymbolAddress((void**)&Sp,  g_S);
    cudaGetSymbolAddress((void**)&STp, g_stat);

    dim3 gq(NQ / 128, 2), gkv(M / 128, 2);
    sgemm_nt<0><<<gq, 256>>>(x, Wq, bq, Qp, NQ);
    sgemm_nt<0><<<gkv, 256>>>(Ep, Wk, bk, Kp, M);
    sgemm_nt<0><<<gkv, 256>>>(Em, Wv, bv, Vp, M);
    convK<<<(M * H * 4) / 256, 256>>>(Kp, Kcp);

    cudaFuncSetAttribute(score_kernel, cudaFuncAttributeMaxDynamicSharedMemorySize, A_TOTAL);
    for (int h0 = 0; h0 < H; h0 += HS) {
        score_kernel<<<dim3(NQ / QB, HS), 512, A_TOTAL>>>(Qp, Kcp, Sp, STp, h0);
        select_kernel<<<(HS * NQ) / 8, 256>>>(Sp, STp, Vp, CTXp, h0);
    }

    sgemm_nt<0><<<gq, 256>>>(CTXp, Wo, bo, ATTp, NQ);
    add_ln<<<NQ / 8, 256>>>(x, ATTp, g1, be1, X1p);
    sgemm_nt<1><<<gq, 256>>>(X1p, W1, b1, Hp, NQ);
    sgemm_nt<0><<<gq, 256>>>(Hp, W2, b2, FFp, NQ);
    add_ln<<<NQ / 8, 256>>>(X1p, FFp, g2, be2, out);
}